// round 2
// baseline (speedup 1.0000x reference)
#include <cuda_runtime.h>

#define Bz 32768
#define Dd 2048
#define Ld 64
#define NC 64

typedef unsigned long long ull;

// Scratch (no allocations allowed)
static __device__ float g_Cq[NC * Dd];   // E @ W_dec_q + b_dec_q
static __device__ float g_Esq[NC];
static __device__ int   g_k[Bz];

union F2U { ull u; float2 f; };

// packed f32x2 FMA: d.lo += a.lo*b.lo ; d.hi += a.hi*b.hi  (real FFMA2 on sm_103a)
__device__ __forceinline__ void ffma2(ull& d, ull a, ull b) {
    asm("fma.rn.f32x2 %0, %1, %2, %0;" : "+l"(d) : "l"(a), "l"(b));
}

// ---------------------------------------------------------------------------
// K0: C_q[c][d] = sum_l E[c][l]*W_dec_q[l][d] + b_dec_q[d];  E^2 per code
// ---------------------------------------------------------------------------
__global__ void k_precompute(const float* __restrict__ E,
                             const float* __restrict__ Wdq,
                             const float* __restrict__ bdq) {
    __shared__ float Es[Ld];
    int c = blockIdx.x;
    if (threadIdx.x < Ld) Es[threadIdx.x] = E[c * Ld + threadIdx.x];
    __syncthreads();
    for (int d = threadIdx.x; d < Dd; d += blockDim.x) {
        float acc = bdq[d];
#pragma unroll
        for (int l = 0; l < Ld; l++) acc = fmaf(Es[l], Wdq[l * Dd + d], acc);
        g_Cq[c * Dd + d] = acc;
    }
    if (threadIdx.x == 0) {
        float s = 0.f;
#pragma unroll
        for (int l = 0; l < Ld; l++) s = fmaf(Es[l], Es[l], s);
        g_Esq[c] = s;
    }
}

// ---------------------------------------------------------------------------
// K1: z_e = x @ W_enc + b_enc   [32768,2048]x[2048,64]
// FFMA2 k-packed. Tile 128 rows x 64 cols, K-chunk 32. 256 thr, 8x4/thread.
// Thread cols interleaved: col = tx + c*16  (conflict-free LDS.64 on ws).
// ---------------------------------------------------------------------------
__global__ __launch_bounds__(256, 2) void k_enc(const float* __restrict__ x,
                                                const float* __restrict__ Wenc,
                                                const float* __restrict__ benc,
                                                float* __restrict__ ze) {
    __shared__ float xs[128][34];   // [row][k], stride 17*8B (odd units)
    __shared__ float ws[64][34];    // [col][k] transposed
    int tid = threadIdx.x;
    int tx = tid & 15, ty = tid >> 4;
    int row0 = blockIdx.x * 128;
    ull acc[8][4] = {};

    for (int k0 = 0; k0 < Dd; k0 += 32) {
#pragma unroll
        for (int i = 0; i < 2; i++) {               // x: 128 rows x 32 k
            int t = tid + i * 256;                  // 0..511
            int r = t >> 2, kq = (t & 3) * 8;
            const float* src = &x[(size_t)(row0 + r) * Dd + k0 + kq];
            float4 v0 = *(const float4*)src;
            float4 v1 = *(const float4*)(src + 4);
            float* d = &xs[r][kq];
            *(float2*)(d + 0) = make_float2(v0.x, v0.y);
            *(float2*)(d + 2) = make_float2(v0.z, v0.w);
            *(float2*)(d + 4) = make_float2(v1.x, v1.y);
            *(float2*)(d + 6) = make_float2(v1.z, v1.w);
        }
#pragma unroll
        for (int i = 0; i < 2; i++) {               // W: 32 k x 64 cols -> transposed
            int t = tid + i * 256;
            int kk = t >> 4, cg = (t & 15) * 4;
            float4 w = *(const float4*)&Wenc[(size_t)(k0 + kk) * Ld + cg];
            ws[cg + 0][kk] = w.x; ws[cg + 1][kk] = w.y;
            ws[cg + 2][kk] = w.z; ws[cg + 3][kk] = w.w;
        }
        __syncthreads();
#pragma unroll
        for (int kk = 0; kk < 32; kk += 2) {
            ull a2[8], b2[4];
#pragma unroll
            for (int r = 0; r < 8; r++) a2[r] = *(const ull*)&xs[ty * 8 + r][kk];
#pragma unroll
            for (int c = 0; c < 4; c++) b2[c] = *(const ull*)&ws[tx + c * 16][kk];
#pragma unroll
            for (int r = 0; r < 8; r++)
#pragma unroll
                for (int c = 0; c < 4; c++) ffma2(acc[r][c], a2[r], b2[c]);
        }
        __syncthreads();
    }
    float be[4];
#pragma unroll
    for (int c = 0; c < 4; c++) be[c] = benc[tx + c * 16];
#pragma unroll
    for (int r = 0; r < 8; r++) {
        int row = row0 + ty * 8 + r;
#pragma unroll
        for (int c = 0; c < 4; c++) {
            F2U u; u.u = acc[r][c];
            ze[(size_t)row * Ld + tx + c * 16] = u.f.x + u.f.y + be[c];
        }
    }
}

// ---------------------------------------------------------------------------
// K_assign: distances, argmin, z_q, neighbors, k, z_dist_flat (unchanged)
// ---------------------------------------------------------------------------
__global__ __launch_bounds__(256) void k_assign(const float* __restrict__ ze,
                                                const float* __restrict__ E,
                                                float* __restrict__ zq,
                                                float* __restrict__ nb,
                                                float* __restrict__ kout,
                                                float* __restrict__ zdist) {
    __shared__ float Es[NC][Ld];
    __shared__ float Esq_s[NC];
    int tid = threadIdx.x;
#pragma unroll
    for (int i = 0; i < 4; i++) {
        int idx = tid + i * 256;
        ((float4*)Es)[idx] = ((const float4*)E)[idx];
    }
    if (tid < NC) Esq_s[tid] = g_Esq[tid];
    __syncthreads();

    int row = blockIdx.x * 256 + tid;
    const float* zr = ze + (size_t)row * Ld;
    float4 z4[16];
#pragma unroll
    for (int j = 0; j < 16; j++) z4[j] = *(const float4*)&zr[j * 4];
    float ze2 = 0.f;
#pragma unroll
    for (int j = 0; j < 16; j++) {
        ze2 = fmaf(z4[j].x, z4[j].x, ze2);
        ze2 = fmaf(z4[j].y, z4[j].y, ze2);
        ze2 = fmaf(z4[j].z, z4[j].z, ze2);
        ze2 = fmaf(z4[j].w, z4[j].w, ze2);
    }

    float best = 3.4e38f; int bk = 0;
    float* zd = zdist + (size_t)row * NC;
    for (int c0 = 0; c0 < NC; c0 += 4) {
        float dvals[4];
#pragma unroll
        for (int u = 0; u < 4; u++) {
            int c = c0 + u;
            float dot = 0.f;
#pragma unroll
            for (int j = 0; j < 16; j++) {
                float4 e = *(const float4*)&Es[c][j * 4];
                dot = fmaf(z4[j].x, e.x, dot);
                dot = fmaf(z4[j].y, e.y, dot);
                dot = fmaf(z4[j].z, e.z, dot);
                dot = fmaf(z4[j].w, e.w, dot);
            }
            float dcur = ze2 - 2.f * dot + Esq_s[c];
            dvals[u] = dcur;
            if (dcur < best) { best = dcur; bk = c; }
        }
        *(float4*)&zd[c0] = make_float4(dvals[0], dvals[1], dvals[2], dvals[3]);
    }

    kout[row] = (float)bk;
    g_k[row] = bk;
    int k1 = bk >> 3, k2 = bk & 7;

    float* zqr = zq + (size_t)row * Ld;
    float* nbr = nb + (size_t)row * 5 * Ld;
    const float4* eb = (const float4*)&Es[bk][0];
#pragma unroll
    for (int j = 0; j < 16; j++) {
        float4 v = eb[j];
        *(float4*)&zqr[j * 4] = v;
        *(float4*)&nbr[j * 4] = v;
    }
    const float4 zero4 = make_float4(0.f, 0.f, 0.f, 0.f);
    {
        bool ok = (k1 < 7); int idx = ok ? ((k1 + 1) * 8 + k2) : 0;
        const float4* e = (const float4*)&Es[idx][0];
#pragma unroll
        for (int j = 0; j < 16; j++) *(float4*)&nbr[64 + j * 4] = ok ? e[j] : zero4;
    }
    {
        bool ok = (k1 > 0); int idx = ok ? ((k1 - 1) * 8 + k2) : 0;
        const float4* e = (const float4*)&Es[idx][0];
#pragma unroll
        for (int j = 0; j < 16; j++) *(float4*)&nbr[128 + j * 4] = ok ? e[j] : zero4;
    }
    {
#pragma unroll
        for (int j = 0; j < 16; j++) *(float4*)&nbr[192 + j * 4] = zero4;
    }
    {
        bool ok = (k2 > 0); int idx = ok ? (k1 * 8 + k2 - 1) : 0;
        const float4* e = (const float4*)&Es[idx][0];
#pragma unroll
        for (int j = 0; j < 16; j++) *(float4*)&nbr[256 + j * 4] = ok ? e[j] : zero4;
    }
}

// ---------------------------------------------------------------------------
// K2: x_e = z_e @ W_dec_e + b_dec_e  [32768,64]x[64,2048]  (FFMA2 k-packed)
//     + fused x_q[row] = g_Cq[g_k[row]] gather-write for the same tile.
// Tile 128 rows x 64 cols, K-chunks of 32 (2 chunks). grid (256, 32).
// ---------------------------------------------------------------------------
__global__ __launch_bounds__(256, 2) void k_dec(const float* __restrict__ ze,
                                                const float* __restrict__ Wde,
                                                const float* __restrict__ bde,
                                                float* __restrict__ xe,
                                                float* __restrict__ xq) {
    __shared__ float As[128][34];   // [row][k]
    __shared__ float Bs[64][34];    // [col_local][k] transposed
    int tid = threadIdx.x;
    int tx = tid & 15, ty = tid >> 4;
    int row0 = blockIdx.x * 128, c0 = blockIdx.y * 64;
    ull acc[8][4] = {};

    for (int k0 = 0; k0 < Ld; k0 += 32) {
#pragma unroll
        for (int i = 0; i < 2; i++) {               // ze: 128 rows x 32 k
            int t = tid + i * 256;
            int r = t >> 2, kq = (t & 3) * 8;
            const float* src = &ze[(size_t)(row0 + r) * Ld + k0 + kq];
            float4 v0 = *(const float4*)src;
            float4 v1 = *(const float4*)(src + 4);
            float* d = &As[r][kq];
            *(float2*)(d + 0) = make_float2(v0.x, v0.y);
            *(float2*)(d + 2) = make_float2(v0.z, v0.w);
            *(float2*)(d + 4) = make_float2(v1.x, v1.y);
            *(float2*)(d + 6) = make_float2(v1.z, v1.w);
        }
#pragma unroll
        for (int i = 0; i < 2; i++) {               // W: 32 k x 64 cols -> transposed
            int t = tid + i * 256;
            int kk = t >> 4, cg = (t & 15) * 4;
            float4 w = *(const float4*)&Wde[(size_t)(k0 + kk) * Dd + c0 + cg];
            Bs[cg + 0][kk] = w.x; Bs[cg + 1][kk] = w.y;
            Bs[cg + 2][kk] = w.z; Bs[cg + 3][kk] = w.w;
        }
        __syncthreads();
#pragma unroll
        for (int kk = 0; kk < 32; kk += 2) {
            ull a2[8], b2[4];
#pragma unroll
            for (int r = 0; r < 8; r++) a2[r] = *(const ull*)&As[ty * 8 + r][kk];
#pragma unroll
            for (int c = 0; c < 4; c++) b2[c] = *(const ull*)&Bs[tx + c * 16][kk];
#pragma unroll
            for (int r = 0; r < 8; r++)
#pragma unroll
                for (int c = 0; c < 4; c++) ffma2(acc[r][c], a2[r], b2[c]);
        }
        __syncthreads();
    }

    float be[4];
#pragma unroll
    for (int c = 0; c < 4; c++) be[c] = bde[c0 + tx + c * 16];
    int krow[8];
#pragma unroll
    for (int r = 0; r < 8; r++) krow[r] = g_k[row0 + ty * 8 + r];

#pragma unroll
    for (int r = 0; r < 8; r++) {
        int row = row0 + ty * 8 + r;
        const float* cq = &g_Cq[(size_t)krow[r] * Dd + c0];
        float* xer = &xe[(size_t)row * Dd + c0];
        float* xqr = &xq[(size_t)row * Dd + c0];
#pragma unroll
        for (int c = 0; c < 4; c++) {
            int col = tx + c * 16;
            F2U u; u.u = acc[r][c];
            xer[col] = u.f.x + u.f.y + be[c];
            xqr[col] = cq[col];
        }
    }
}

// ---------------------------------------------------------------------------
// Output layout (float32, reference-return order):
//   x_e [B,D] | x_q [B,D] | z_e [B,L] | z_q [B,L] | z_q_neighbors [B,5,L]
//   | k [B] (as float) | z_dist_flat [B,64]
// ---------------------------------------------------------------------------
extern "C" void kernel_launch(void* const* d_in, const int* in_sizes, int n_in,
                              void* d_out, int out_size) {
    const float* x    = (const float*)d_in[0];
    const float* Wenc = (const float*)d_in[1];
    const float* benc = (const float*)d_in[2];
    const float* Wdq  = (const float*)d_in[3];
    const float* bdq  = (const float*)d_in[4];
    const float* Wde  = (const float*)d_in[5];
    const float* bde  = (const float*)d_in[6];
    const float* E    = (const float*)d_in[7];
    float* out = (float*)d_out;

    const size_t OFF_XE = 0;
    const size_t OFF_XQ = (size_t)Bz * Dd;
    const size_t OFF_ZE = 2 * (size_t)Bz * Dd;
    const size_t OFF_ZQ = OFF_ZE + (size_t)Bz * Ld;
    const size_t OFF_NB = OFF_ZQ + (size_t)Bz * Ld;
    const size_t OFF_K  = OFF_NB + (size_t)Bz * 5 * Ld;
    const size_t OFF_ZD = OFF_K + (size_t)Bz;

    k_precompute<<<NC, 256>>>(E, Wdq, bdq);
    k_enc<<<Bz / 128, 256>>>(x, Wenc, benc, out + OFF_ZE);
    k_assign<<<Bz / 256, 256>>>(out + OFF_ZE, E,
                                out + OFF_ZQ, out + OFF_NB,
                                out + OFF_K, out + OFF_ZD);
    k_dec<<<dim3(Bz / 128, Dd / 64), 256>>>(out + OFF_ZE, Wde, bde,
                                            out + OFF_XE, out + OFF_XQ);
}

// round 3
// speedup vs baseline: 1.2428x; 1.2428x over previous
#include <cuda_runtime.h>

#define Bz 32768
#define Dd 2048
#define Ld 64
#define NC 64

typedef unsigned long long ull;

static __device__ float g_Cq[NC * Dd];
static __device__ float g_Esq[NC];
static __device__ int   g_k[Bz];

union F2U { ull u; float2 f; };

// d.lo += a.lo*b.lo ; d.hi += a.hi*b.hi   (FFMA2 on sm_103a)
__device__ __forceinline__ void ffma2(ull& d, ull a, ull b) {
    asm("fma.rn.f32x2 %0, %1, %2, %0;" : "+l"(d) : "l"(a), "l"(b));
}
// broadcast one float into both f32x2 lanes
__device__ __forceinline__ ull pack2(float a) {
    ull r; asm("mov.b64 %0, {%1, %1};" : "=l"(r) : "f"(a)); return r;
}

// ---------------------------------------------------------------------------
// K0: C_q = E @ W_dec_q + b_dec_q ;  E^2 per code
// ---------------------------------------------------------------------------
__global__ void k_precompute(const float* __restrict__ E,
                             const float* __restrict__ Wdq,
                             const float* __restrict__ bdq) {
    __shared__ float Es[Ld];
    int c = blockIdx.x;
    if (threadIdx.x < Ld) Es[threadIdx.x] = E[c * Ld + threadIdx.x];
    __syncthreads();
    for (int d = threadIdx.x; d < Dd; d += blockDim.x) {
        float acc = bdq[d];
#pragma unroll
        for (int l = 0; l < Ld; l++) acc = fmaf(Es[l], Wdq[l * Dd + d], acc);
        g_Cq[c * Dd + d] = acc;
    }
    if (threadIdx.x == 0) {
        float s = 0.f;
#pragma unroll
        for (int l = 0; l < Ld; l++) s = fmaf(Es[l], Es[l], s);
        g_Esq[c] = s;
    }
}

// ---------------------------------------------------------------------------
// K1: z_e = x @ W_enc + b_enc   [32768,2048]x[2048,64]
// Col-pair-packed FFMA2. Tile 32 rows x 64 cols, 64 thr, 4 rows x 8 cols each.
// grid 1024 (near-perfect SM balance).
// ---------------------------------------------------------------------------
__global__ __launch_bounds__(64, 8) void k_enc(const float* __restrict__ x,
                                               const float* __restrict__ Wenc,
                                               const float* __restrict__ benc,
                                               float* __restrict__ ze) {
    __shared__ float As[32][36];    // [row][k] pad 4 (16B-aligned rows)
    __shared__ float Bs[32][64];    // [k][col] natural row-major
    int tid = threadIdx.x;
    int cx = tid & 7, ry = tid >> 3;     // 8 col-threads x 8 row-threads
    int row0 = blockIdx.x * 32;
    ull acc[4][4] = {};                  // [row][colpair]: cols 2(cx+8c)+{0,1}

    for (int k0 = 0; k0 < Dd; k0 += 32) {
#pragma unroll
        for (int i = 0; i < 4; i++) {            // A: 32x32 = 256 float4
            int idx = tid + 64 * i;
            int r = idx >> 3, kq = (idx & 7) * 4;
            *(float4*)&As[r][kq] = *(const float4*)&x[(size_t)(row0 + r) * Dd + k0 + kq];
        }
#pragma unroll
        for (int i = 0; i < 8; i++) {            // B: 32x64 = 512 float4
            int idx = tid + 64 * i;
            int kk = idx >> 4, c4 = (idx & 15) * 4;
            *(float4*)&Bs[kk][c4] = *(const float4*)&Wenc[(size_t)(k0 + kk) * Ld + c4];
        }
        __syncthreads();
#pragma unroll
        for (int k4 = 0; k4 < 32; k4 += 4) {
            float4 a4[4];
#pragma unroll
            for (int r = 0; r < 4; r++) a4[r] = *(const float4*)&As[ry * 4 + r][k4];
#pragma unroll
            for (int j = 0; j < 4; j++) {
                ull b2[4];
#pragma unroll
                for (int c = 0; c < 4; c++)
                    b2[c] = *(const ull*)&Bs[k4 + j][2 * (cx + 8 * c)];
#pragma unroll
                for (int r = 0; r < 4; r++) {
                    float av = (j == 0) ? a4[r].x : (j == 1) ? a4[r].y
                             : (j == 2) ? a4[r].z : a4[r].w;
                    ull a2 = pack2(av);
#pragma unroll
                    for (int c = 0; c < 4; c++) ffma2(acc[r][c], a2, b2[c]);
                }
            }
        }
        __syncthreads();
    }
#pragma unroll
    for (int c = 0; c < 4; c++) {
        int col = 2 * (cx + 8 * c);
        float2 be = *(const float2*)&benc[col];
#pragma unroll
        for (int r = 0; r < 4; r++) {
            F2U u; u.u = acc[r][c];
            *(float2*)&ze[(size_t)(row0 + ry * 4 + r) * Ld + col] =
                make_float2(u.f.x + be.x, u.f.y + be.y);
        }
    }
}

// ---------------------------------------------------------------------------
// K_assign: distances, argmin, z_q, neighbors, k, z_dist_flat
// ---------------------------------------------------------------------------
__global__ __launch_bounds__(256) void k_assign(const float* __restrict__ ze,
                                                const float* __restrict__ E,
                                                float* __restrict__ zq,
                                                float* __restrict__ nb,
                                                float* __restrict__ kout,
                                                float* __restrict__ zdist) {
    __shared__ float Es[NC][Ld];
    __shared__ float Esq_s[NC];
    int tid = threadIdx.x;
#pragma unroll
    for (int i = 0; i < 4; i++) {
        int idx = tid + i * 256;
        ((float4*)Es)[idx] = ((const float4*)E)[idx];
    }
    if (tid < NC) Esq_s[tid] = g_Esq[tid];
    __syncthreads();

    int row = blockIdx.x * 256 + tid;
    const float* zr = ze + (size_t)row * Ld;
    float4 z4[16];
#pragma unroll
    for (int j = 0; j < 16; j++) z4[j] = *(const float4*)&zr[j * 4];
    float ze2 = 0.f;
#pragma unroll
    for (int j = 0; j < 16; j++) {
        ze2 = fmaf(z4[j].x, z4[j].x, ze2);
        ze2 = fmaf(z4[j].y, z4[j].y, ze2);
        ze2 = fmaf(z4[j].z, z4[j].z, ze2);
        ze2 = fmaf(z4[j].w, z4[j].w, ze2);
    }

    float best = 3.4e38f; int bk = 0;
    float* zd = zdist + (size_t)row * NC;
    for (int c0 = 0; c0 < NC; c0 += 4) {
        float dvals[4];
#pragma unroll
        for (int u = 0; u < 4; u++) {
            int c = c0 + u;
            float dot = 0.f;
#pragma unroll
            for (int j = 0; j < 16; j++) {
                float4 e = *(const float4*)&Es[c][j * 4];
                dot = fmaf(z4[j].x, e.x, dot);
                dot = fmaf(z4[j].y, e.y, dot);
                dot = fmaf(z4[j].z, e.z, dot);
                dot = fmaf(z4[j].w, e.w, dot);
            }
            float dcur = ze2 - 2.f * dot + Esq_s[c];
            dvals[u] = dcur;
            if (dcur < best) { best = dcur; bk = c; }
        }
        *(float4*)&zd[c0] = make_float4(dvals[0], dvals[1], dvals[2], dvals[3]);
    }

    kout[row] = (float)bk;
    g_k[row] = bk;
    int k1 = bk >> 3, k2 = bk & 7;

    float* zqr = zq + (size_t)row * Ld;
    float* nbr = nb + (size_t)row * 5 * Ld;
    const float4* eb = (const float4*)&Es[bk][0];
#pragma unroll
    for (int j = 0; j < 16; j++) {
        float4 v = eb[j];
        *(float4*)&zqr[j * 4] = v;
        *(float4*)&nbr[j * 4] = v;
    }
    const float4 zero4 = make_float4(0.f, 0.f, 0.f, 0.f);
    {
        bool ok = (k1 < 7); int idx = ok ? ((k1 + 1) * 8 + k2) : 0;
        const float4* e = (const float4*)&Es[idx][0];
#pragma unroll
        for (int j = 0; j < 16; j++) *(float4*)&nbr[64 + j * 4] = ok ? e[j] : zero4;
    }
    {
        bool ok = (k1 > 0); int idx = ok ? ((k1 - 1) * 8 + k2) : 0;
        const float4* e = (const float4*)&Es[idx][0];
#pragma unroll
        for (int j = 0; j < 16; j++) *(float4*)&nbr[128 + j * 4] = ok ? e[j] : zero4;
    }
    {
#pragma unroll
        for (int j = 0; j < 16; j++) *(float4*)&nbr[192 + j * 4] = zero4;
    }
    {
        bool ok = (k2 > 0); int idx = ok ? (k1 * 8 + k2 - 1) : 0;
        const float4* e = (const float4*)&Es[idx][0];
#pragma unroll
        for (int j = 0; j < 16; j++) *(float4*)&nbr[256 + j * 4] = ok ? e[j] : zero4;
    }
}

// ---------------------------------------------------------------------------
// K2: x_e = z_e @ W_dec_e + b_dec_e  [32768,64]x[64,2048] + fused x_q gather.
// Col-pair-packed FFMA2. Tile 128 rows x 128 cols, 256 thr, 8x8 per thread.
// grid (256, 16).
// ---------------------------------------------------------------------------
__global__ __launch_bounds__(256, 2) void k_dec(const float* __restrict__ ze,
                                                const float* __restrict__ Wde,
                                                const float* __restrict__ bde,
                                                float* __restrict__ xe,
                                                float* __restrict__ xq) {
    __shared__ float As[128][36];   // [row][k]
    __shared__ float Bs[32][128];   // [k][col] natural
    int tid = threadIdx.x;
    int tx = tid & 15, ty = tid >> 4;
    int row0 = blockIdx.x * 128, c0 = blockIdx.y * 128;
    ull acc[8][4] = {};             // [row][colpair]: cols c0 + 2(tx+16c)+{0,1}

    for (int k0 = 0; k0 < Ld; k0 += 32) {
#pragma unroll
        for (int i = 0; i < 4; i++) {            // A: 128x32 = 1024 float4
            int idx = tid + 256 * i;
            int r = idx >> 3, kq = (idx & 7) * 4;
            *(float4*)&As[r][kq] = *(const float4*)&ze[(size_t)(row0 + r) * Ld + k0 + kq];
        }
#pragma unroll
        for (int i = 0; i < 4; i++) {            // B: 32x128 = 1024 float4
            int idx = tid + 256 * i;
            int kk = idx >> 5, c4 = (idx & 31) * 4;
            *(float4*)&Bs[kk][c4] = *(const float4*)&Wde[(size_t)(k0 + kk) * Dd + c0 + c4];
        }
        __syncthreads();
#pragma unroll
        for (int k4 = 0; k4 < 32; k4 += 4) {
            float4 a4[8];
#pragma unroll
            for (int r = 0; r < 8; r++) a4[r] = *(const float4*)&As[ty * 8 + r][k4];
#pragma unroll
            for (int j = 0; j < 4; j++) {
                ull b2[4];
#pragma unroll
                for (int c = 0; c < 4; c++)
                    b2[c] = *(const ull*)&Bs[k4 + j][2 * (tx + 16 * c)];
#pragma unroll
                for (int r = 0; r < 8; r++) {
                    float av = (j == 0) ? a4[r].x : (j == 1) ? a4[r].y
                             : (j == 2) ? a4[r].z : a4[r].w;
                    ull a2 = pack2(av);
#pragma unroll
                    for (int c = 0; c < 4; c++) ffma2(acc[r][c], a2, b2[c]);
                }
            }
        }
        __syncthreads();
    }

    int rowb = row0 + ty * 8;
    int krow[8];
#pragma unroll
    for (int r = 0; r < 8; r++) krow[r] = g_k[rowb + r];
#pragma unroll
    for (int c = 0; c < 4; c++) {
        int col = c0 + 2 * (tx + 16 * c);
        float2 be = *(const float2*)&bde[col];
#pragma unroll
        for (int r = 0; r < 8; r++) {
            F2U u; u.u = acc[r][c];
            *(float2*)&xe[(size_t)(rowb + r) * Dd + col] =
                make_float2(u.f.x + be.x, u.f.y + be.y);
            *(float2*)&xq[(size_t)(rowb + r) * Dd + col] =
                *(const float2*)&g_Cq[(size_t)krow[r] * Dd + col];
        }
    }
}

// ---------------------------------------------------------------------------
extern "C" void kernel_launch(void* const* d_in, const int* in_sizes, int n_in,
                              void* d_out, int out_size) {
    const float* x    = (const float*)d_in[0];
    const float* Wenc = (const float*)d_in[1];
    const float* benc = (const float*)d_in[2];
    const float* Wdq  = (const float*)d_in[3];
    const float* bdq  = (const float*)d_in[4];
    const float* Wde  = (const float*)d_in[5];
    const float* bde  = (const float*)d_in[6];
    const float* E    = (const float*)d_in[7];
    float* out = (float*)d_out;

    const size_t OFF_XE = 0;
    const size_t OFF_XQ = (size_t)Bz * Dd;
    const size_t OFF_ZE = 2 * (size_t)Bz * Dd;
    const size_t OFF_ZQ = OFF_ZE + (size_t)Bz * Ld;
    const size_t OFF_NB = OFF_ZQ + (size_t)Bz * Ld;
    const size_t OFF_K  = OFF_NB + (size_t)Bz * 5 * Ld;
    const size_t OFF_ZD = OFF_K + (size_t)Bz;

    k_precompute<<<NC, 256>>>(E, Wdq, bdq);
    k_enc<<<Bz / 32, 64>>>(x, Wenc, benc, out + OFF_ZE);
    k_assign<<<Bz / 256, 256>>>(out + OFF_ZE, E,
                                out + OFF_ZQ, out + OFF_NB,
                                out + OFF_K, out + OFF_ZD);
    k_dec<<<dim3(Bz / 128, Dd / 128), 256>>>(out + OFF_ZE, Wde, bde,
                                             out + OFF_XE, out + OFF_XQ);
}

// round 4
// speedup vs baseline: 1.4361x; 1.1555x over previous
#include <cuda_runtime.h>

#define Bz 32768
#define Dd 2048
#define Ld 64
#define NC 64

typedef unsigned long long ull;
typedef unsigned int uint;

static __device__ float g_Cq[NC * Dd];
static __device__ float g_Esq[NC];
static __device__ int   g_k[Bz];

union F2U { ull u; float2 f; };

__device__ __forceinline__ void ffma2(ull& d, ull a, ull b) {
    asm("fma.rn.f32x2 %0, %1, %2, %0;" : "+l"(d) : "l"(a), "l"(b));
}
__device__ __forceinline__ ull pack2(float a) {
    ull r; asm("mov.b64 %0, {%1, %1};" : "=l"(r) : "f"(a)); return r;
}
__device__ __forceinline__ void cp16(void* s, const void* g) {
    uint sa = (uint)__cvta_generic_to_shared(s);
    asm volatile("cp.async.cg.shared.global [%0], [%1], 16;" :: "r"(sa), "l"(g));
}
#define CP_COMMIT asm volatile("cp.async.commit_group;")
#define CP_WAIT0  asm volatile("cp.async.wait_group 0;")

// ---------------------------------------------------------------------------
// K0: C_q = E @ W_dec_q + b_dec_q ;  E^2 per code
// ---------------------------------------------------------------------------
__global__ void k_precompute(const float* __restrict__ E,
                             const float* __restrict__ Wdq,
                             const float* __restrict__ bdq) {
    __shared__ float Es[Ld];
    int c = blockIdx.x;
    if (threadIdx.x < Ld) Es[threadIdx.x] = E[c * Ld + threadIdx.x];
    __syncthreads();
    for (int d = threadIdx.x; d < Dd; d += blockDim.x) {
        float acc = bdq[d];
#pragma unroll
        for (int l = 0; l < Ld; l++) acc = fmaf(Es[l], Wdq[l * Dd + d], acc);
        g_Cq[c * Dd + d] = acc;
    }
    if (threadIdx.x == 0) {
        float s = 0.f;
#pragma unroll
        for (int l = 0; l < Ld; l++) s = fmaf(Es[l], Es[l], s);
        g_Esq[c] = s;
    }
}

// ---------------------------------------------------------------------------
// K1: z_e = x @ W_enc + b_enc  [32768,2048]x[2048,64]
// cp.async double-buffered, 1 sync/chunk. Tile 32x64, 64 thr, 4 rows x 8 cols.
// ---------------------------------------------------------------------------
__global__ __launch_bounds__(64, 8) void k_enc(const float* __restrict__ x,
                                               const float* __restrict__ Wenc,
                                               const float* __restrict__ benc,
                                               float* __restrict__ ze) {
    __shared__ float As[2][32][36];   // [row][k], pad->144B rows (16B-aligned)
    __shared__ float Bs[2][32][64];   // [k][col]
    int tid = threadIdx.x;
    int cx = tid & 7, ry = tid >> 3;
    int row0 = blockIdx.x * 32;
    ull acc[4][4] = {};   // [r][2g+h] -> cols 4cx+32g+2h+{0,1}

#define STAGE_ENC(buf, k0)                                                     \
    {                                                                          \
        _Pragma("unroll")                                                      \
        for (int j = 0; j < 4; j++) {            /* A: 256 f4 */               \
            int idx = tid + 64 * j;                                            \
            int r = idx >> 3, kq = (idx & 7) * 4;                              \
            cp16(&As[buf][r][kq], &x[(size_t)(row0 + r) * Dd + (k0) + kq]);    \
        }                                                                      \
        _Pragma("unroll")                                                      \
        for (int j = 0; j < 8; j++) {            /* B: 512 f4 */               \
            int idx = tid + 64 * j;                                            \
            int kk = idx >> 4, c4 = (idx & 15) * 4;                            \
            cp16(&Bs[buf][kk][c4], &Wenc[(size_t)((k0) + kk) * Ld + c4]);      \
        }                                                                      \
        CP_COMMIT;                                                             \
    }

    STAGE_ENC(0, 0);
    CP_WAIT0;
    __syncthreads();

    for (int c = 0; c < 64; c++) {
        int p = c & 1;
        if (c < 63) STAGE_ENC(p ^ 1, (c + 1) * 32);
#pragma unroll
        for (int k4 = 0; k4 < 32; k4 += 4) {
            float4 a4[4];
#pragma unroll
            for (int r = 0; r < 4; r++) a4[r] = *(const float4*)&As[p][ry * 4 + r][k4];
#pragma unroll
            for (int j = 0; j < 4; j++) {
                ull b[4];
#pragma unroll
                for (int g = 0; g < 2; g++) {
                    b[2 * g]     = *(const ull*)&Bs[p][k4 + j][4 * cx + 32 * g];
                    b[2 * g + 1] = *(const ull*)&Bs[p][k4 + j][4 * cx + 32 * g + 2];
                }
#pragma unroll
                for (int r = 0; r < 4; r++) {
                    float av = (j == 0) ? a4[r].x : (j == 1) ? a4[r].y
                             : (j == 2) ? a4[r].z : a4[r].w;
                    ull a2 = pack2(av);
#pragma unroll
                    for (int cc = 0; cc < 4; cc++) ffma2(acc[r][cc], a2, b[cc]);
                }
            }
        }
        if (c < 63) CP_WAIT0;
        __syncthreads();
    }
#pragma unroll
    for (int g = 0; g < 2; g++) {
        int col = 4 * cx + 32 * g;
        float4 be = *(const float4*)&benc[col];
#pragma unroll
        for (int r = 0; r < 4; r++) {
            F2U u0, u1; u0.u = acc[r][2 * g]; u1.u = acc[r][2 * g + 1];
            float4 o = make_float4(u0.f.x + be.x, u0.f.y + be.y,
                                   u1.f.x + be.z, u1.f.y + be.w);
            *(float4*)&ze[(size_t)(row0 + ry * 4 + r) * Ld + col] = o;
        }
    }
#undef STAGE_ENC
}

// ---------------------------------------------------------------------------
// K_assign: distances, argmin, z_q, neighbors, k, z_dist_flat
// ---------------------------------------------------------------------------
__global__ __launch_bounds__(256) void k_assign(const float* __restrict__ ze,
                                                const float* __restrict__ E,
                                                float* __restrict__ zq,
                                                float* __restrict__ nb,
                                                float* __restrict__ kout,
                                                float* __restrict__ zdist) {
    __shared__ float Es[NC][Ld];
    __shared__ float Esq_s[NC];
    int tid = threadIdx.x;
#pragma unroll
    for (int i = 0; i < 4; i++) {
        int idx = tid + i * 256;
        ((float4*)Es)[idx] = ((const float4*)E)[idx];
    }
    if (tid < NC) Esq_s[tid] = g_Esq[tid];
    __syncthreads();

    int row = blockIdx.x * 256 + tid;
    const float* zr = ze + (size_t)row * Ld;
    float4 z4[16];
#pragma unroll
    for (int j = 0; j < 16; j++) z4[j] = *(const float4*)&zr[j * 4];
    float ze2 = 0.f;
#pragma unroll
    for (int j = 0; j < 16; j++) {
        ze2 = fmaf(z4[j].x, z4[j].x, ze2);
        ze2 = fmaf(z4[j].y, z4[j].y, ze2);
        ze2 = fmaf(z4[j].z, z4[j].z, ze2);
        ze2 = fmaf(z4[j].w, z4[j].w, ze2);
    }

    float best = 3.4e38f; int bk = 0;
    float* zd = zdist + (size_t)row * NC;
    for (int c0 = 0; c0 < NC; c0 += 4) {
        float dvals[4];
#pragma unroll
        for (int u = 0; u < 4; u++) {
            int c = c0 + u;
            float dot = 0.f;
#pragma unroll
            for (int j = 0; j < 16; j++) {
                float4 e = *(const float4*)&Es[c][j * 4];
                dot = fmaf(z4[j].x, e.x, dot);
                dot = fmaf(z4[j].y, e.y, dot);
                dot = fmaf(z4[j].z, e.z, dot);
                dot = fmaf(z4[j].w, e.w, dot);
            }
            float dcur = ze2 - 2.f * dot + Esq_s[c];
            dvals[u] = dcur;
            if (dcur < best) { best = dcur; bk = c; }
        }
        *(float4*)&zd[c0] = make_float4(dvals[0], dvals[1], dvals[2], dvals[3]);
    }

    kout[row] = (float)bk;
    g_k[row] = bk;
    int k1 = bk >> 3, k2 = bk & 7;

    float* zqr = zq + (size_t)row * Ld;
    float* nbr = nb + (size_t)row * 5 * Ld;
    const float4* eb = (const float4*)&Es[bk][0];
#pragma unroll
    for (int j = 0; j < 16; j++) {
        float4 v = eb[j];
        *(float4*)&zqr[j * 4] = v;
        *(float4*)&nbr[j * 4] = v;
    }
    const float4 zero4 = make_float4(0.f, 0.f, 0.f, 0.f);
    {
        bool ok = (k1 < 7); int idx = ok ? ((k1 + 1) * 8 + k2) : 0;
        const float4* e = (const float4*)&Es[idx][0];
#pragma unroll
        for (int j = 0; j < 16; j++) *(float4*)&nbr[64 + j * 4] = ok ? e[j] : zero4;
    }
    {
        bool ok = (k1 > 0); int idx = ok ? ((k1 - 1) * 8 + k2) : 0;
        const float4* e = (const float4*)&Es[idx][0];
#pragma unroll
        for (int j = 0; j < 16; j++) *(float4*)&nbr[128 + j * 4] = ok ? e[j] : zero4;
    }
    {
#pragma unroll
        for (int j = 0; j < 16; j++) *(float4*)&nbr[192 + j * 4] = zero4;
    }
    {
        bool ok = (k2 > 0); int idx = ok ? (k1 * 8 + k2 - 1) : 0;
        const float4* e = (const float4*)&Es[idx][0];
#pragma unroll
        for (int j = 0; j < 16; j++) *(float4*)&nbr[256 + j * 4] = ok ? e[j] : zero4;
    }
}

// ---------------------------------------------------------------------------
// K2: x_e = z_e@W_dec_e + b  [32768,64]x[64,2048] + fused x_q gather.
// SINGLE stage (full K=64), one sync. As swizzled 32KB + Bs 16KB = 48KB.
// Tile 128 rows x 64 cols, 256 thr, 8 rows x 4 cols each. grid (256,32).
// ---------------------------------------------------------------------------
__device__ __forceinline__ int asw(int row, int u) {   // u = 16B unit 0..15
    return row * 64 + ((u ^ ((row >> 3) & 1)) << 2);   // float offset
}

__global__ __launch_bounds__(256, 2) void k_dec(const float* __restrict__ ze,
                                                const float* __restrict__ Wde,
                                                const float* __restrict__ bde,
                                                float* __restrict__ xe,
                                                float* __restrict__ xq) {
    __shared__ float As[128 * 64];   // swizzled [row][k]
    __shared__ float Bs[64][64];     // [k][col]
    int tid = threadIdx.x;
    int tx = tid & 15, ty = tid >> 4;
    int row0 = blockIdx.x * 128, c0 = blockIdx.y * 64;

#pragma unroll
    for (int j = 0; j < 8; j++) {                // A: 2048 f4
        int idx = tid + 256 * j;
        int r = idx >> 4, u = idx & 15;
        cp16(&As[asw(r, u)], &ze[(size_t)(row0 + r) * Ld + u * 4]);
    }
#pragma unroll
    for (int j = 0; j < 4; j++) {                // B: 1024 f4
        int idx = tid + 256 * j;
        int kk = idx >> 4, c4 = (idx & 15) * 4;
        cp16(&Bs[kk][c4], &Wde[(size_t)kk * Dd + c0 + c4]);
    }
    CP_COMMIT;
    CP_WAIT0;
    __syncthreads();

    ull acc[8][2] = {};              // cols 4tx + 2h + {0,1}
#pragma unroll
    for (int k4 = 0; k4 < 64; k4 += 4) {
        float4 a4[8];
#pragma unroll
        for (int r = 0; r < 8; r++)
            a4[r] = *(const float4*)&As[asw(ty * 8 + r, k4 >> 2)];
#pragma unroll
        for (int j = 0; j < 4; j++) {
            ull b0 = *(const ull*)&Bs[k4 + j][4 * tx];
            ull b1 = *(const ull*)&Bs[k4 + j][4 * tx + 2];
#pragma unroll
            for (int r = 0; r < 8; r++) {
                float av = (j == 0) ? a4[r].x : (j == 1) ? a4[r].y
                         : (j == 2) ? a4[r].z : a4[r].w;
                ull a2 = pack2(av);
                ffma2(acc[r][0], a2, b0);
                ffma2(acc[r][1], a2, b1);
            }
        }
    }

    int rowb = row0 + ty * 8;
    int col = c0 + 4 * tx;
    float4 be = *(const float4*)&bde[col];
    int krow[8];
#pragma unroll
    for (int r = 0; r < 8; r++) krow[r] = g_k[rowb + r];
#pragma unroll
    for (int r = 0; r < 8; r++) {
        F2U u0, u1; u0.u = acc[r][0]; u1.u = acc[r][1];
        float4 o = make_float4(u0.f.x + be.x, u0.f.y + be.y,
                               u1.f.x + be.z, u1.f.y + be.w);
        *(float4*)&xe[(size_t)(rowb + r) * Dd + col] = o;
        *(float4*)&xq[(size_t)(rowb + r) * Dd + col] =
            *(const float4*)&g_Cq[(size_t)krow[r] * Dd + col];
    }
}

// ---------------------------------------------------------------------------
extern "C" void kernel_launch(void* const* d_in, const int* in_sizes, int n_in,
                              void* d_out, int out_size) {
    const float* x    = (const float*)d_in[0];
    const float* Wenc = (const float*)d_in[1];
    const float* benc = (const float*)d_in[2];
    const float* Wdq  = (const float*)d_in[3];
    const float* bdq  = (const float*)d_in[4];
    const float* Wde  = (const float*)d_in[5];
    const float* bde  = (const float*)d_in[6];
    const float* E    = (const float*)d_in[7];
    float* out = (float*)d_out;

    const size_t OFF_XE = 0;
    const size_t OFF_XQ = (size_t)Bz * Dd;
    const size_t OFF_ZE = 2 * (size_t)Bz * Dd;
    const size_t OFF_ZQ = OFF_ZE + (size_t)Bz * Ld;
    const size_t OFF_NB = OFF_ZQ + (size_t)Bz * Ld;
    const size_t OFF_K  = OFF_NB + (size_t)Bz * 5 * Ld;
    const size_t OFF_ZD = OFF_K + (size_t)Bz;

    k_precompute<<<NC, 256>>>(E, Wdq, bdq);
    k_enc<<<Bz / 32, 64>>>(x, Wenc, benc, out + OFF_ZE);
    k_assign<<<Bz / 256, 256>>>(out + OFF_ZE, E,
                                out + OFF_ZQ, out + OFF_NB,
                                out + OFF_K, out + OFF_ZD);
    k_dec<<<dim3(Bz / 128, Dd / 64), 256>>>(out + OFF_ZE, Wde, bde,
                                            out + OFF_XE, out + OFF_XQ);
}